// round 2
// baseline (speedup 1.0000x reference)
#include <cuda_runtime.h>

#define NN 100000
#define NE 3200000
#define FIN 512
#define HID 16
#define NC 64

// ---------------- scratch (static device globals; no allocation) ----------------
__device__ __align__(16) float g_bufA[NN * HID];
__device__ __align__(16) float g_bufB[NN * HID];
__device__ __align__(128) float g_row[NN * 32];   // per node: [hn[16] | h_raw[16]] (128B row)
__device__ int g_counts[NN + 1];
__device__ int g_rowptr[NN + 1];
__device__ int g_cursor[NN];
__device__ int g_colsrc[NE];

__constant__ __align__(16) float cW1[FIN * HID];
__constant__ __align__(16) float cB1[HID];
__constant__ __align__(16) float cW2[HID * NC];
__constant__ __align__(16) float cB2[NC];

// ---------------- small helpers ----------------
__device__ __forceinline__ float d4(float4 a, float4 b) {
    return a.x * b.x + a.y * b.y + a.z * b.z + a.w * b.w;
}
__device__ __forceinline__ float4 scl4(float4 a, float c) {
    return make_float4(a.x * c, a.y * c, a.z * c, a.w * c);
}
__device__ __forceinline__ unsigned long long pk2(float a, float b) {
    unsigned long long r;
    asm("mov.b64 %0, {%1, %2};" : "=l"(r) : "f"(a), "f"(b));
    return r;
}
__device__ __forceinline__ void upk2(unsigned long long v, float& a, float& b) {
    asm("mov.b64 {%0, %1}, %2;" : "=f"(a), "=f"(b) : "l"(v));
}
__device__ __forceinline__ void ffma2(unsigned long long& d, unsigned long long a, unsigned long long b) {
    asm("fma.rn.f32x2 %0, %1, %2, %0;" : "+l"(d) : "l"(a), "l"(b));
}

// ---------------- CSR build ----------------
__global__ void k_zero(int n) {
    int i = blockIdx.x * blockDim.x + threadIdx.x;
    if (i < n) g_counts[i] = 0;
}

__global__ void k_hist(const int* __restrict__ ei, int E) {
    int t = blockIdx.x * blockDim.x + threadIdx.x;
    int E4 = E >> 2;
    const int4* d4p = (const int4*)(ei + E);
    if (t < E4) {
        int4 d = __ldg(d4p + t);
        atomicAdd(&g_counts[d.x], 1);
        atomicAdd(&g_counts[d.y], 1);
        atomicAdd(&g_counts[d.z], 1);
        atomicAdd(&g_counts[d.w], 1);
    }
    if (t == 0) {
        for (int e = E4 * 4; e < E; e++) atomicAdd(&g_counts[ei[E + e]], 1);
    }
}

// single-block exclusive scan over g_counts[0..NN) -> g_rowptr, g_cursor
__global__ void k_scan(int n) {
    __shared__ int ssum[1024];
    const int CH = 128;  // 1024*128 = 131072 >= NN
    int t = threadIdx.x;
    int base = t * CH;
    int s = 0;
    for (int i = 0; i < CH; i++) {
        int idx = base + i;
        if (idx < n) s += g_counts[idx];
    }
    ssum[t] = s;
    __syncthreads();
    for (int off = 1; off < 1024; off <<= 1) {
        int v = (t >= off) ? ssum[t - off] : 0;
        __syncthreads();
        ssum[t] += v;
        __syncthreads();
    }
    int excl = (t == 0) ? 0 : ssum[t - 1];
    for (int i = 0; i < CH; i++) {
        int idx = base + i;
        if (idx < n) {
            g_rowptr[idx] = excl;
            g_cursor[idx] = excl;
            excl += g_counts[idx];
        }
    }
    if (t == 1023) g_rowptr[n] = ssum[1023];
}

__global__ void k_scatter(const int* __restrict__ ei, int E) {
    int t = blockIdx.x * blockDim.x + threadIdx.x;
    int E4 = E >> 2;
    const int4* s4p = (const int4*)ei;
    const int4* d4p = (const int4*)(ei + E);
    if (t < E4) {
        int4 s = __ldg(s4p + t);
        int4 d = __ldg(d4p + t);
        int p;
        p = atomicAdd(&g_cursor[d.x], 1); g_colsrc[p] = s.x;
        p = atomicAdd(&g_cursor[d.y], 1); g_colsrc[p] = s.y;
        p = atomicAdd(&g_cursor[d.z], 1); g_colsrc[p] = s.z;
        p = atomicAdd(&g_cursor[d.w], 1); g_colsrc[p] = s.w;
    }
    if (t == 0) {
        for (int e = E4 * 4; e < E; e++) {
            int p = atomicAdd(&g_cursor[ei[E + e]], 1);
            g_colsrc[p] = ei[e];
        }
    }
}

// ---------------- h = relu(x @ W1 + b1), thread-per-row, packed f32x2 FMA ----------------
__global__ void k_gemm1(const float4* __restrict__ x4, int n) {
    int row = blockIdx.x * blockDim.x + threadIdx.x;
    if (row >= n) return;
    unsigned long long acc[8];
#pragma unroll
    for (int j = 0; j < 8; j++) acc[j] = pk2(cB1[2 * j], cB1[2 * j + 1]);

    const float4* xr = x4 + (long)row * (FIN / 4);
#pragma unroll 2
    for (int q = 0; q < FIN / 4; q++) {
        float4 xv = __ldg(xr + q);
#pragma unroll
        for (int c = 0; c < 4; c++) {
            float xs = (c == 0) ? xv.x : (c == 1) ? xv.y : (c == 2) ? xv.z : xv.w;
            unsigned long long xx = pk2(xs, xs);
            const longlong2* w = (const longlong2*)&cW1[(q * 4 + c) * HID];
#pragma unroll
            for (int j = 0; j < 4; j++) {
                longlong2 wp = w[j];
                ffma2(acc[2 * j], xx, (unsigned long long)wp.x);
                ffma2(acc[2 * j + 1], xx, (unsigned long long)wp.y);
            }
        }
    }
    float o[16];
#pragma unroll
    for (int j = 0; j < 8; j++) {
        float a, b;
        upk2(acc[j], a, b);
        o[2 * j] = fmaxf(a, 0.f);
        o[2 * j + 1] = fmaxf(b, 0.f);
    }
    float4* o4 = (float4*)&g_bufA[(long)row * HID];
#pragma unroll
    for (int j = 0; j < 4; j++)
        o4[j] = make_float4(o[4 * j], o[4 * j + 1], o[4 * j + 2], o[4 * j + 3]);
}

// ---------------- build per-node 128B row: [hn | h_raw] ----------------
__global__ void k_norm(int srcSel, int n) {
    int i = blockIdx.x * blockDim.x + threadIdx.x;
    if (i >= n) return;
    const float4* h4 = (const float4*)(srcSel ? g_bufB : g_bufA);
    float4 v0 = h4[i * 4 + 0], v1 = h4[i * 4 + 1], v2 = h4[i * 4 + 2], v3 = h4[i * 4 + 3];
    float ss = d4(v0, v0) + d4(v1, v1) + d4(v2, v2) + d4(v3, v3);
    float inv = 1.0f / fmaxf(sqrtf(ss), 1e-12f);
    float4* r4 = (float4*)&g_row[(long)i * 32];
    r4[0] = scl4(v0, inv);
    r4[1] = scl4(v1, inv);
    r4[2] = scl4(v2, inv);
    r4[3] = scl4(v3, inv);
    r4[4] = v0; r4[5] = v1; r4[6] = v2; r4[7] = v3;
}

// ---------------- AGNN layer: warp/node, 8 lanes per edge (1 line per edge gather) ----------------
__global__ void k_agnn(const float* __restrict__ beta_p, int outSel, int n) {
    int lane = threadIdx.x & 31;
    int warp = threadIdx.x >> 5;
    int node = blockIdx.x * 8 + warp;
    if (node >= n) return;
    int sub = lane & 7;    // which 16B chunk of the 128B row
    int slot = lane >> 3;  // which of 4 concurrent edges
    float beta = __ldg(beta_p);
    const float4* row4 = (const float4*)g_row;

    float4 dv = row4[(long)node * 8 + sub];  // sub<4: hn chunk of dst; sub>=4: raw-h chunk

    // self-loop cosine = hn . hn (computed same way as reference)
    float ps = (sub < 4) ? d4(dv, dv) : 0.f;
    ps += __shfl_xor_sync(0xffffffffu, ps, 1, 8);
    ps += __shfl_xor_sync(0xffffffffu, ps, 2, 8);
    ps += __shfl_xor_sync(0xffffffffu, ps, 4, 8);
    float cos_self = ps;

    float m, s;
    float4 a;
    if (slot == 0) {
        m = beta * cos_self;
        s = 1.f;
        a = (sub >= 4) ? dv : make_float4(0, 0, 0, 0);
    } else {
        m = -1e30f;
        s = 0.f;
        a = make_float4(0, 0, 0, 0);
    }

    int e0 = g_rowptr[node];
    int cnt = g_rowptr[node + 1] - e0;
    for (int base = 0; base < cnt; base += 4) {
        int idx = base + slot;
        bool v = idx < cnt;
        int sn = v ? __ldg(&g_colsrc[e0 + idx]) : 0;  // 8 lanes share one address
        float4 sv = __ldg(&row4[(long)sn * 8 + sub]); // one 128B line per edge
        float pp = (sub < 4) ? d4(dv, sv) : 0.f;
        pp += __shfl_xor_sync(0xffffffffu, pp, 1, 8);
        pp += __shfl_xor_sync(0xffffffffu, pp, 2, 8);
        pp += __shfl_xor_sync(0xffffffffu, pp, 4, 8);
        float lg = v ? beta * pp : -1e30f;
        float M = fmaxf(m, lg);
        float r = __expf(m - M);
        float p = v ? __expf(lg - M) : 0.f;
        s = s * r + p;
        a.x = a.x * r + p * sv.x;
        a.y = a.y * r + p * sv.y;
        a.z = a.z * r + p * sv.z;
        a.w = a.w * r + p * sv.w;
        m = M;
    }

    // combine the 4 slot states (lane bits 3,4)
#pragma unroll
    for (int off = 8; off <= 16; off <<= 1) {
        float m2 = __shfl_xor_sync(0xffffffffu, m, off);
        float s2 = __shfl_xor_sync(0xffffffffu, s, off);
        float bx = __shfl_xor_sync(0xffffffffu, a.x, off);
        float by = __shfl_xor_sync(0xffffffffu, a.y, off);
        float bz = __shfl_xor_sync(0xffffffffu, a.z, off);
        float bw = __shfl_xor_sync(0xffffffffu, a.w, off);
        float M = fmaxf(m, m2);
        float pa = __expf(m - M);
        float pb = __expf(m2 - M);
        s = s * pa + s2 * pb;
        a.x = a.x * pa + bx * pb;
        a.y = a.y * pa + by * pb;
        a.z = a.z * pa + bz * pb;
        a.w = a.w * pa + bw * pb;
        m = M;
    }

    if (sub >= 4) {
        float inv = 1.0f / s;
        float4* out4 = (float4*)(outSel ? g_bufB : g_bufA);
        out4[(long)node * 4 + (sub - 4)] = scl4(a, inv);
    }
}

// ---------------- out = log_softmax(h @ W2 + b2), warp-per-row ----------------
__global__ void k_gemm2(int srcSel, float* __restrict__ out, int n) {
    __shared__ float sW[HID * NC];
    __shared__ float sB[NC];
    for (int i = threadIdx.x; i < HID * NC; i += blockDim.x) sW[i] = cW2[i];
    if (threadIdx.x < NC) sB[threadIdx.x] = cB2[threadIdx.x];
    __syncthreads();

    int warp = threadIdx.x >> 5, lane = threadIdx.x & 31;
    int row = blockIdx.x * (blockDim.x >> 5) + warp;
    if (row >= n) return;

    const float* h = srcSel ? g_bufB : g_bufA;
    float hv = (lane < HID) ? h[(long)row * HID + lane] : 0.f;
    float z0 = sB[lane], z1 = sB[lane + 32];
#pragma unroll
    for (int k = 0; k < HID; k++) {
        float hk = __shfl_sync(0xffffffffu, hv, k);
        z0 += hk * sW[k * NC + lane];
        z1 += hk * sW[k * NC + 32 + lane];
    }
    float mx = fmaxf(z0, z1);
#pragma unroll
    for (int off = 16; off > 0; off >>= 1) mx = fmaxf(mx, __shfl_xor_sync(0xffffffffu, mx, off));
    float p = __expf(z0 - mx) + __expf(z1 - mx);
#pragma unroll
    for (int off = 16; off > 0; off >>= 1) p += __shfl_xor_sync(0xffffffffu, p, off);
    float lse = mx + __logf(p);
    out[(long)row * NC + lane] = z0 - lse;
    out[(long)row * NC + 32 + lane] = z1 - lse;
}

// ---------------- launch ----------------
extern "C" void kernel_launch(void* const* d_in, const int* in_sizes, int n_in,
                              void* d_out, int out_size) {
    const float* x = (const float*)d_in[0];
    const int* ei = (const int*)d_in[1];   // [2, E] int32
    const float* W1 = (const float*)d_in[2];
    const float* b1 = (const float*)d_in[3];
    const float* W2 = (const float*)d_in[4];
    const float* b2 = (const float*)d_in[5];
    const float* beta1 = (const float*)d_in[6];
    const float* beta2 = (const float*)d_in[7];
    float* out = (float*)d_out;

    int N = in_sizes[0] / FIN;
    int E = in_sizes[1] / 2;

    cudaMemcpyToSymbolAsync(cW1, W1, FIN * HID * sizeof(float), 0, cudaMemcpyDeviceToDevice, 0);
    cudaMemcpyToSymbolAsync(cB1, b1, HID * sizeof(float), 0, cudaMemcpyDeviceToDevice, 0);
    cudaMemcpyToSymbolAsync(cW2, W2, HID * NC * sizeof(float), 0, cudaMemcpyDeviceToDevice, 0);
    cudaMemcpyToSymbolAsync(cB2, b2, NC * sizeof(float), 0, cudaMemcpyDeviceToDevice, 0);

    // CSR build (by dst)
    k_zero<<<(N + 255) / 256, 256>>>(N);
    k_hist<<<(E / 4 + 255) / 256, 256>>>(ei, E);
    k_scan<<<1, 1024>>>(N);
    k_scatter<<<(E / 4 + 255) / 256, 256>>>(ei, E);

    // MLP in
    k_gemm1<<<(N + 255) / 256, 256>>>((const float4*)x, N);

    // layer 1: bufA -> bufB
    k_norm<<<(N + 255) / 256, 256>>>(0, N);
    k_agnn<<<(N + 7) / 8, 256>>>(beta1, 1, N);

    // layer 2: bufB -> bufA
    k_norm<<<(N + 255) / 256, 256>>>(1, N);
    k_agnn<<<(N + 7) / 8, 256>>>(beta2, 0, N);

    // MLP out + log_softmax
    k_gemm2<<<(N + 7) / 8, 256>>>(0, out, N);
}